// round 11
// baseline (speedup 1.0000x reference)
#include <cuda_runtime.h>
#include <cuda_bf16.h>
#include <cstdint>

#define N_NODES  100000
#define N_EDGES  600000
#define N_GRAPHS 2000
#define HID      128
#define LAYERS   6
#define SA       136               // bf16 row stride in smem
#define NODES_PT 64                // nodes per tile
#define NT       ((N_NODES + NODES_PT - 1) / NODES_PT)   // 1563
#define NBLK     148
#define NTHREADS 384               // 8 consumer warps + 4 producer warps
#define IDXCAP   1024              // staged csr indices per tile slot
#define SCAN_B   1024
#define SCAN_NB  ((N_NODES + SCAN_B - 1) / SCAN_B)

// named barrier IDs
#define BAR_FULL0   1
#define BAR_FULL1   2
#define BAR_EMPTY0  3
#define BAR_EMPTY1  4
#define BAR_CONS    5
#define BAR_PROD    6

// ---------------------------------------------------------------------------
// Persistent scratch (allocation-free). Ping-pong x buffers: layer l reads
// buf[l&1], writes buf[1-(l&1)] -> producers never race with consumers.
// ---------------------------------------------------------------------------
__device__ float g_xa[(size_t)N_NODES * HID];
__device__ float g_xb[(size_t)N_NODES * HID];
__device__ __align__(16) __nv_bfloat16 g_wt[(size_t)2 * 2 * LAYERS * HID * SA];
// CSR scratch
__device__ int g_deg[N_NODES];
__device__ int g_rowstart[N_NODES + 1];
__device__ int g_cursor[N_NODES];
__device__ int g_blocksum[SCAN_NB];
__device__ int g_csr[N_EDGES];

// ---------------------------------------------------------------------------
// helpers
// ---------------------------------------------------------------------------
__device__ __forceinline__ uint32_t smem_u32(const void* p) {
    uint32_t a;
    asm("{ .reg .u64 t; cvta.to.shared.u64 t, %1; cvt.u32.u64 %0, t; }"
        : "=r"(a) : "l"(p));
    return a;
}
__device__ __forceinline__ void ldm_x4(uint32_t (&r)[4], uint32_t addr) {
    asm volatile("ldmatrix.sync.aligned.m8n8.x4.shared.b16 {%0,%1,%2,%3}, [%4];"
                 : "=r"(r[0]), "=r"(r[1]), "=r"(r[2]), "=r"(r[3]) : "r"(addr));
}
__device__ __forceinline__ void mma16816(float (&d)[4], const uint32_t (&a)[4],
                                         uint32_t b0, uint32_t b1) {
    asm volatile(
        "mma.sync.aligned.m16n8k16.row.col.f32.bf16.bf16.f32 "
        "{%0,%1,%2,%3}, {%4,%5,%6,%7}, {%8,%9}, {%0,%1,%2,%3};"
        : "+f"(d[0]), "+f"(d[1]), "+f"(d[2]), "+f"(d[3])
        : "r"(a[0]), "r"(a[1]), "r"(a[2]), "r"(a[3]), "r"(b0), "r"(b1));
}
__device__ __forceinline__ uint32_t pk(__nv_bfloat16 a, __nv_bfloat16 b) {
    return (uint32_t)__bfloat16_as_ushort(a) |
           ((uint32_t)__bfloat16_as_ushort(b) << 16);
}
#define BAR_SYNC(id, cnt) \
    asm volatile("bar.sync %0, %1;" :: "r"(id), "r"(cnt) : "memory")
#define BAR_ARRIVE(id, cnt) \
    asm volatile("bar.arrive %0, %1;" :: "r"(id), "r"(cnt) : "memory")

// ---------------------------------------------------------------------------
// Embedding lookup -> g_xa (also zeroes g_deg to save a launch)
// ---------------------------------------------------------------------------
__global__ void embed_kernel(const int* __restrict__ tok,
                             const float* __restrict__ emb) {
    int i = blockIdx.x * blockDim.x + threadIdx.x;
    if (i >= N_NODES * 32) return;
    if (i < N_NODES) g_deg[i] = 0;
    int node = i >> 5, d = i & 31;
    ((float4*)g_xa)[i] = ((const float4*)emb)[tok[node] * 32 + d];
}

// ---------------------------------------------------------------------------
// CSR build
// ---------------------------------------------------------------------------
__global__ void k_hist(const int* __restrict__ ei) {
    int i = blockIdx.x * blockDim.x + threadIdx.x;
    if (i < N_EDGES) atomicAdd(&g_deg[ei[N_EDGES + i]], 1);
}
__global__ void k_scan1() {
    __shared__ int sm[SCAN_B];
    int tid = threadIdx.x;
    int i = blockIdx.x * SCAN_B + tid;
    int v = (i < N_NODES) ? g_deg[i] : 0;
    sm[tid] = v;
    __syncthreads();
#pragma unroll
    for (int o = 1; o < SCAN_B; o <<= 1) {
        int t = (tid >= o) ? sm[tid - o] : 0;
        __syncthreads();
        sm[tid] += t;
        __syncthreads();
    }
    if (i < N_NODES) g_rowstart[i] = sm[tid] - v;
    if (tid == SCAN_B - 1) g_blocksum[blockIdx.x] = sm[tid];
}
__global__ void k_scan2() {
    if (threadIdx.x == 0) {
        int run = 0;
        for (int b = 0; b < SCAN_NB; b++) {
            int t = g_blocksum[b];
            g_blocksum[b] = run;
            run += t;
        }
        g_rowstart[N_NODES] = run;
    }
}
__global__ void k_scan3() {
    int i = blockIdx.x * blockDim.x + threadIdx.x;
    if (i < N_NODES) {
        int r = g_rowstart[i] + g_blocksum[i / SCAN_B];
        g_rowstart[i] = r;
        g_cursor[i] = r;
    }
}
__global__ void k_fill(const int* __restrict__ ei) {
    int i = blockIdx.x * blockDim.x + threadIdx.x;
    if (i < N_EDGES) {
        int dst = ei[N_EDGES + i];
        g_csr[atomicAdd(&g_cursor[dst], 1)] = ei[i];
    }
}

// ---------------------------------------------------------------------------
// Weight prep: split W[k][c] -> transposed hi/lo images Wt[c][k], stride SA.
// ---------------------------------------------------------------------------
__global__ void prep_w(const float* __restrict__ W1, const float* __restrict__ W2) {
    int i = blockIdx.x * blockDim.x + threadIdx.x;
    if (i >= 2 * LAYERS * HID * HID) return;
    int which = i / (LAYERS * HID * HID);
    int r = i % (LAYERS * HID * HID);
    int l = r / (HID * HID);
    int kc = r % (HID * HID);
    int k = kc / HID, c = kc % HID;
    const float* W = which ? W2 : W1;
    float v = W[(size_t)l * HID * HID + k * HID + c];
    __nv_bfloat16 hi = __float2bfloat16(v);
    __nv_bfloat16 lo = __float2bfloat16(v - __bfloat162float(hi));
    size_t img = (size_t)which * LAYERS + l;
    size_t o = img * HID * SA + (size_t)c * SA + k;
    g_wt[o] = hi;
    g_wt[(size_t)2 * LAYERS * HID * SA + o] = lo;
}

// ---------------------------------------------------------------------------
// Fused persistent gather + GIN MLP, warp-specialized.
// warps 0-7: GEMM consumers.  warps 8-11: gather producers (read x_in).
// Producers stage the tile's contiguous csr range into smem first, so the
// x-row loads have no dependent-index chains.
// ---------------------------------------------------------------------------
#define WTILE_B   (HID * SA * 2)          // 34816
#define AHALF_B   (NODES_PT * SA * 2)     // 17408
#define ABUF_B    (2 * AHALF_B)           // 34816
#define IDX_OFF   (4 * WTILE_B + 2 * ABUF_B)       // 208896
#define SMEM_BYTES (IDX_OFF + 2 * IDXCAP * 4)      // 217088

// 3-product split GEMM over a 32x32 warp tile.
__device__ __forceinline__ void gemm_warp(
    uint32_t aAhi, uint32_t aAlo, uint32_t aWh, uint32_t aWl,
    int m0, int n0, int arow_off, int akoff, int brow_off, int bkoff,
    float (&acc)[2][4][4])
{
#pragma unroll
    for (int kb = 0; kb < HID; kb += 16) {
        uint32_t ah[2][4], al[2][4];
#pragma unroll
        for (int s = 0; s < 2; s++) {
            uint32_t ro = (uint32_t)((m0 + s * 16 + arow_off) * SA + kb + akoff) * 2;
            ldm_x4(ah[s], aAhi + ro);
            ldm_x4(al[s], aAlo + ro);
        }
#pragma unroll
        for (int nb = 0; nb < 2; nb++) {
            uint32_t bh[4], bl[4];
            uint32_t ro = (uint32_t)((n0 + nb * 16 + brow_off) * SA + kb + bkoff) * 2;
            ldm_x4(bh, aWh + ro);
            ldm_x4(bl, aWl + ro);
#pragma unroll
            for (int s = 0; s < 2; s++) {
                mma16816(acc[s][2 * nb],     ah[s], bh[0], bh[1]);
                mma16816(acc[s][2 * nb],     ah[s], bl[0], bl[1]);
                mma16816(acc[s][2 * nb],     al[s], bh[0], bh[1]);
                mma16816(acc[s][2 * nb + 1], ah[s], bh[2], bh[3]);
                mma16816(acc[s][2 * nb + 1], ah[s], bl[2], bl[3]);
                mma16816(acc[s][2 * nb + 1], al[s], bh[2], bh[3]);
            }
        }
    }
}

__global__ void __launch_bounds__(NTHREADS, 1) mlp_fused(
    const float* __restrict__ b1, const float* __restrict__ b2, int l,
    int parity)   // parity 0: read g_xa write g_xb; 1: read g_xb write g_xa
{
    extern __shared__ __align__(16) char S[];
    uint32_t base = smem_u32(S);
    uint32_t aW1h = base, aW1l = base + WTILE_B;
    uint32_t aW2h = base + 2 * WTILE_B, aW2l = base + 3 * WTILE_B;
    uint32_t aBuf[2] = { base + 4 * WTILE_B, base + 4 * WTILE_B + ABUF_B };
    char* pBuf[2] = { S + 4 * WTILE_B, S + 4 * WTILE_B + ABUF_B };
    int* s_idx = (int*)(S + IDX_OFF);     // [2][IDXCAP]

    const float* xin = parity ? g_xb : g_xa;
    float*       xout = parity ? g_xa : g_xb;

    int tid = threadIdx.x, warp = tid >> 5, lane = tid & 31;
    int bid = blockIdx.x;

    // ---- stage all weights once (all 384 threads) ----
    {
        const size_t istr = (size_t)HID * SA;
        const size_t lstr = (size_t)2 * LAYERS * HID * SA;
        const float4* srcs[4] = {
            (const float4*)(g_wt + (size_t)l * istr),
            (const float4*)(g_wt + lstr + (size_t)l * istr),
            (const float4*)(g_wt + (size_t)(LAYERS + l) * istr),
            (const float4*)(g_wt + lstr + (size_t)(LAYERS + l) * istr) };
#pragma unroll
        for (int q = 0; q < 4; q++) {
            float4* d = (float4*)(S + q * WTILE_B);
            for (int i = tid; i < WTILE_B / 16; i += NTHREADS) d[i] = srcs[q][i];
        }
    }
    __syncthreads();

    if (warp >= 8) {
        // ================= PRODUCER: stage csr, gather, split ===============
        int pw = warp - 8;                    // 0..3
        int ptid = tid - 256;                 // 0..127
        const float4* x4 = (const float4*)xin;
        int it = 0;
        for (int t = bid; t < NT; t += NBLK, it++) {
            int s = it & 1;
            if (it >= 2) BAR_SYNC(BAR_EMPTY0 + s, NTHREADS);
            int node0 = t * NODES_PT;
            char* pA = pBuf[s];
            int* idx = s_idx + s * IDXCAP;

            // stage this tile's contiguous csr index range (coalesced)
            int ebase = __ldg(g_rowstart + node0);
            int hi_n = node0 + NODES_PT; if (hi_n > N_NODES) hi_n = N_NODES;
            int cnt = __ldg(g_rowstart + hi_n) - ebase;
            int stg = cnt < IDXCAP ? cnt : IDXCAP;
            for (int j = ptid; j < stg; j += 128) idx[j] = __ldg(g_csr + ebase + j);
            BAR_SYNC(BAR_PROD, 128);          // indices visible to all producers

            for (int i = pw; i < NODES_PT; i += 4) {
                int n = node0 + i;
                float4 v = make_float4(0.f, 0.f, 0.f, 0.f);
                if (n < N_NODES) {
                    v = x4[(size_t)n * 32 + lane];
                    int re0 = __ldg(g_rowstart + n) - ebase;
                    int re1 = __ldg(g_rowstart + n + 1) - ebase;
                    for (int e = re0; e < re1; e++) {
                        int src = (e < IDXCAP) ? idx[e] : __ldg(g_csr + ebase + e);
                        float4 u = x4[(size_t)src * 32 + lane];
                        v.x += u.x; v.y += u.y; v.z += u.z; v.w += u.w;
                    }
                }
                __nv_bfloat16 h0 = __float2bfloat16(v.x), h1 = __float2bfloat16(v.y);
                __nv_bfloat16 h2 = __float2bfloat16(v.z), h3 = __float2bfloat16(v.w);
                __nv_bfloat16 q0 = __float2bfloat16(v.x - __bfloat162float(h0));
                __nv_bfloat16 q1 = __float2bfloat16(v.y - __bfloat162float(h1));
                __nv_bfloat16 q2 = __float2bfloat16(v.z - __bfloat162float(h2));
                __nv_bfloat16 q3 = __float2bfloat16(v.w - __bfloat162float(h3));
                uint32_t off = (uint32_t)(i * SA + lane * 4) * 2;
                *(uint2*)(pA + off) = make_uint2(pk(h0, h1), pk(h2, h3));
                *(uint2*)(pA + AHALF_B + off) = make_uint2(pk(q0, q1), pk(q2, q3));
            }
            BAR_ARRIVE(BAR_FULL0 + s, NTHREADS);
        }
    } else {
        // ================= CONSUMER: 2 GEMMs + epilogues ====================
        int m0 = (warp >> 2) * 32;
        int n0 = (warp & 3) * 32;
        int g = lane >> 3;
        int arow_off = (lane & 7) + ((g & 1) << 3);
        int akoff    = (g >> 1) << 3;
        int brow_off = (lane & 7) + ((g >> 1) << 3);
        int bkoff    = (g & 1) << 3;

        float b1v[4][2], b2v[4][2];
#pragma unroll
        for (int j = 0; j < 4; j++) {
            int col = n0 + j * 8 + (lane & 3) * 2;
            b1v[j][0] = __ldg(b1 + col); b1v[j][1] = __ldg(b1 + col + 1);
            b2v[j][0] = __ldg(b2 + col); b2v[j][1] = __ldg(b2 + col + 1);
        }

        int it = 0;
        for (int t = bid; t < NT; t += NBLK, it++) {
            int s = it & 1;
            int node0 = t * NODES_PT;
            BAR_SYNC(BAR_FULL0 + s, NTHREADS);   // wait A tile

            uint32_t aAhi = aBuf[s], aAlo = aBuf[s] + AHALF_B;
            char* pA = pBuf[s];

            float acc[2][4][4];
#pragma unroll
            for (int q = 0; q < 2; q++)
#pragma unroll
                for (int j = 0; j < 4; j++)
#pragma unroll
                    for (int c = 0; c < 4; c++) acc[q][j][c] = 0.f;

            gemm_warp(aAhi, aAlo, aW1h, aW1l, m0, n0,
                      arow_off, akoff, brow_off, bkoff, acc);
            BAR_SYNC(BAR_CONS, 256);   // all consumers done reading A

            // epilogue 1: h = relu(acc + b1) -> overwrite A buf (hi/lo)
            {
                int r0 = m0 + (lane >> 2);
#pragma unroll
                for (int j = 0; j < 4; j++) {
                    int col = n0 + j * 8 + (lane & 3) * 2;
#pragma unroll
                    for (int q = 0; q < 2; q++) {
                        int rA = r0 + q * 16, rB = rA + 8;
                        float v0 = fmaxf(acc[q][j][0] + b1v[j][0], 0.f);
                        float v1 = fmaxf(acc[q][j][1] + b1v[j][1], 0.f);
                        float v2 = fmaxf(acc[q][j][2] + b1v[j][0], 0.f);
                        float v3 = fmaxf(acc[q][j][3] + b1v[j][1], 0.f);
                        __nv_bfloat16 h0 = __float2bfloat16(v0), h1 = __float2bfloat16(v1);
                        __nv_bfloat16 h2 = __float2bfloat16(v2), h3 = __float2bfloat16(v3);
                        __nv_bfloat16 p0 = __float2bfloat16(v0 - __bfloat162float(h0));
                        __nv_bfloat16 p1 = __float2bfloat16(v1 - __bfloat162float(h1));
                        __nv_bfloat16 p2 = __float2bfloat16(v2 - __bfloat162float(h2));
                        __nv_bfloat16 p3 = __float2bfloat16(v3 - __bfloat162float(h3));
                        uint32_t oA = (uint32_t)(rA * SA + col) * 2;
                        uint32_t oB = (uint32_t)(rB * SA + col) * 2;
                        *(uint32_t*)(pA + oA) = pk(h0, h1);
                        *(uint32_t*)(pA + AHALF_B + oA) = pk(p0, p1);
                        *(uint32_t*)(pA + oB) = pk(h2, h3);
                        *(uint32_t*)(pA + AHALF_B + oB) = pk(p2, p3);
                    }
                }
            }
            BAR_SYNC(BAR_CONS, 256);   // H complete

#pragma unroll
            for (int q = 0; q < 2; q++)
#pragma unroll
                for (int j = 0; j < 4; j++)
#pragma unroll
                    for (int c = 0; c < 4; c++) acc[q][j][c] = 0.f;

            gemm_warp(aAhi, aAlo, aW2h, aW2l, m0, n0,
                      arow_off, akoff, brow_off, bkoff, acc);
            BAR_ARRIVE(BAR_EMPTY0 + s, NTHREADS);   // buffer free for producer

            // epilogue 2: relu(acc + b2) -> xout
            {
                int r0 = m0 + (lane >> 2);
#pragma unroll
                for (int j = 0; j < 4; j++) {
                    int col = n0 + j * 8 + (lane & 3) * 2;
#pragma unroll
                    for (int q = 0; q < 2; q++) {
                        int rA = r0 + q * 16, rB = rA + 8;
                        int gA = node0 + rA, gB = node0 + rB;
                        if (gA < N_NODES) {
                            float2 v = make_float2(fmaxf(acc[q][j][0] + b2v[j][0], 0.f),
                                                   fmaxf(acc[q][j][1] + b2v[j][1], 0.f));
                            *(float2*)(xout + (size_t)gA * HID + col) = v;
                        }
                        if (gB < N_NODES) {
                            float2 v = make_float2(fmaxf(acc[q][j][2] + b2v[j][0], 0.f),
                                                   fmaxf(acc[q][j][3] + b2v[j][1], 0.f));
                            *(float2*)(xout + (size_t)gB * HID + col) = v;
                        }
                    }
                }
            }
        }
    }
}

// ---------------------------------------------------------------------------
// Global mean pool (reads g_xa: LAYERS is even so final x lands there)
// ---------------------------------------------------------------------------
__global__ void pool_kernel(const int* __restrict__ batch,
                            float* __restrict__ out) {
    int g = blockIdx.x;
    __shared__ int s_range[2];
    if (threadIdx.x == 0) {
        int lo = 0, hi = N_NODES;
        while (lo < hi) { int m = (lo + hi) >> 1; if (batch[m] < g) lo = m + 1; else hi = m; }
        s_range[0] = lo;
        lo = 0; hi = N_NODES;
        while (lo < hi) { int m = (lo + hi) >> 1; if (batch[m] < g + 1) lo = m + 1; else hi = m; }
        s_range[1] = lo;
    }
    __syncthreads();
    int start = s_range[0], end = s_range[1];
    float sum = 0.f;
    for (int n = start; n < end; n++)
        sum += g_xa[(size_t)n * HID + threadIdx.x];
    float cnt = (float)(end - start);
    out[g * HID + threadIdx.x] = sum / fmaxf(cnt, 1.0f);
}

// ---------------------------------------------------------------------------
// Inputs: x_tokens, edge_index, batch, emb, W1, b1, W2, b2
// ---------------------------------------------------------------------------
extern "C" void kernel_launch(void* const* d_in, const int* in_sizes, int n_in,
                              void* d_out, int out_size) {
    const int*   tok   = (const int*)  d_in[0];
    const int*   ei    = (const int*)  d_in[1];
    const int*   batch = (const int*)  d_in[2];
    const float* emb   = (const float*)d_in[3];
    const float* W1    = (const float*)d_in[4];
    const float* b1    = (const float*)d_in[5];
    const float* W2    = (const float*)d_in[6];
    const float* b2    = (const float*)d_in[7];
    float* out = (float*)d_out;

    cudaFuncSetAttribute(mlp_fused, cudaFuncAttributeMaxDynamicSharedMemorySize,
                         SMEM_BYTES);

    prep_w<<<(2 * LAYERS * HID * HID + 255) / 256, 256>>>(W1, W2);
    embed_kernel<<<(N_NODES * 32 + 255) / 256, 256>>>(tok, emb);

    k_hist <<<(N_EDGES + 255) / 256, 256>>>(ei);
    k_scan1<<<SCAN_NB, SCAN_B>>>();
    k_scan2<<<1, 32>>>();
    k_scan3<<<(N_NODES + 255) / 256, 256>>>();
    k_fill <<<(N_EDGES + 255) / 256, 256>>>(ei);

    for (int l = 0; l < LAYERS; l++) {
        mlp_fused<<<NBLK, NTHREADS, SMEM_BYTES>>>(
            b1 + (size_t)l * HID, b2 + (size_t)l * HID, l, l & 1);
    }

    pool_kernel<<<N_GRAPHS, HID>>>(batch, out);
}

// round 12
// speedup vs baseline: 2.2609x; 2.2609x over previous
#include <cuda_runtime.h>
#include <cuda_bf16.h>
#include <cstdint>

#define N_NODES  100000
#define N_PAD    100096            // 1564 * 64
#define N_EDGES  600000
#define N_GRAPHS 2000
#define HID      128
#define LAYERS   6
#define SA       136               // bf16 row stride in smem (272 B)
#define NODES_PT 64                // nodes per tile
#define NT       (N_PAD / NODES_PT)  // 1564 tiles
#define NBLK     148
#define SCAN_B   1024
#define SCAN_NB  ((N_NODES + SCAN_B - 1) / SCAN_B)

// ---------------------------------------------------------------------------
// Persistent scratch (allocation-free)
// ---------------------------------------------------------------------------
__device__ float g_x[(size_t)N_NODES * HID];
__device__ __align__(16) __nv_bfloat16 g_aggh[(size_t)N_PAD * HID];  // pad rows stay 0
__device__ __align__(16) __nv_bfloat16 g_aggl[(size_t)N_PAD * HID];
__device__ __align__(16) __nv_bfloat16 g_wt[(size_t)2 * 2 * LAYERS * HID * SA];
// CSR scratch
__device__ int g_deg[N_NODES];
__device__ int g_rowstart[N_NODES + 1];
__device__ int g_cursor[N_NODES];
__device__ int g_blocksum[SCAN_NB];
__device__ int g_csr[N_EDGES];

// ---------------------------------------------------------------------------
// helpers
// ---------------------------------------------------------------------------
__device__ __forceinline__ uint32_t smem_u32(const void* p) {
    uint32_t a;
    asm("{ .reg .u64 t; cvta.to.shared.u64 t, %1; cvt.u32.u64 %0, t; }"
        : "=r"(a) : "l"(p));
    return a;
}
__device__ __forceinline__ void ldm_x4(uint32_t (&r)[4], uint32_t addr) {
    asm volatile("ldmatrix.sync.aligned.m8n8.x4.shared.b16 {%0,%1,%2,%3}, [%4];"
                 : "=r"(r[0]), "=r"(r[1]), "=r"(r[2]), "=r"(r[3]) : "r"(addr));
}
__device__ __forceinline__ void mma16816(float (&d)[4], const uint32_t (&a)[4],
                                         uint32_t b0, uint32_t b1) {
    asm volatile(
        "mma.sync.aligned.m16n8k16.row.col.f32.bf16.bf16.f32 "
        "{%0,%1,%2,%3}, {%4,%5,%6,%7}, {%8,%9}, {%0,%1,%2,%3};"
        : "+f"(d[0]), "+f"(d[1]), "+f"(d[2]), "+f"(d[3])
        : "r"(a[0]), "r"(a[1]), "r"(a[2]), "r"(a[3]), "r"(b0), "r"(b1));
}
__device__ __forceinline__ uint32_t pk(__nv_bfloat16 a, __nv_bfloat16 b) {
    return (uint32_t)__bfloat16_as_ushort(a) |
           ((uint32_t)__bfloat16_as_ushort(b) << 16);
}
#define CP16(dst, src) \
    asm volatile("cp.async.cg.shared.global [%0], [%1], 16;" \
                 :: "r"(dst), "l"(src) : "memory")
#define CP_COMMIT()  asm volatile("cp.async.commit_group;" ::: "memory")
#define CP_WAIT(n)   asm volatile("cp.async.wait_group %0;" :: "n"(n) : "memory")

// ---------------------------------------------------------------------------
// Embedding lookup (also zeroes g_deg, saving a launch)
// ---------------------------------------------------------------------------
__global__ void embed_kernel(const int* __restrict__ tok,
                             const float* __restrict__ emb) {
    int i = blockIdx.x * blockDim.x + threadIdx.x;
    if (i >= N_NODES * 32) return;
    if (i < N_NODES) g_deg[i] = 0;
    int node = i >> 5, d = i & 31;
    ((float4*)g_x)[i] = ((const float4*)emb)[tok[node] * 32 + d];
}

// ---------------------------------------------------------------------------
// CSR build
// ---------------------------------------------------------------------------
__global__ void k_hist(const int* __restrict__ ei) {
    int i = blockIdx.x * blockDim.x + threadIdx.x;
    if (i < N_EDGES) atomicAdd(&g_deg[ei[N_EDGES + i]], 1);
}
__global__ void k_scan1() {
    __shared__ int sm[SCAN_B];
    int tid = threadIdx.x;
    int i = blockIdx.x * SCAN_B + tid;
    int v = (i < N_NODES) ? g_deg[i] : 0;
    sm[tid] = v;
    __syncthreads();
#pragma unroll
    for (int o = 1; o < SCAN_B; o <<= 1) {
        int t = (tid >= o) ? sm[tid - o] : 0;
        __syncthreads();
        sm[tid] += t;
        __syncthreads();
    }
    if (i < N_NODES) g_rowstart[i] = sm[tid] - v;
    if (tid == SCAN_B - 1) g_blocksum[blockIdx.x] = sm[tid];
}
__global__ void k_scan2() {
    if (threadIdx.x == 0) {
        int run = 0;
        for (int b = 0; b < SCAN_NB; b++) {
            int t = g_blocksum[b];
            g_blocksum[b] = run;
            run += t;
        }
        g_rowstart[N_NODES] = run;
    }
}
__global__ void k_scan3() {
    int i = blockIdx.x * blockDim.x + threadIdx.x;
    if (i < N_NODES) {
        int r = g_rowstart[i] + g_blocksum[i / SCAN_B];
        g_rowstart[i] = r;
        g_cursor[i] = r;
    }
}
__global__ void k_fill(const int* __restrict__ ei) {
    int i = blockIdx.x * blockDim.x + threadIdx.x;
    if (i < N_EDGES) {
        int dst = ei[N_EDGES + i];
        g_csr[atomicAdd(&g_cursor[dst], 1)] = ei[i];
    }
}

// ---------------------------------------------------------------------------
// Gather: agg[n] = x[n] + sum_e x[csr[e]]; 4-wide ILP so 4 row-loads are in
// flight before any accumulate (in-order issue would otherwise serialize at
// one load per ~300-600 cyc). Writes pre-split bf16 hi/lo.
// ---------------------------------------------------------------------------
__global__ void __launch_bounds__(256) gather_kernel() {
    int w = (blockIdx.x * blockDim.x + threadIdx.x) >> 5;
    int lane = threadIdx.x & 31;
    if (w >= N_NODES) return;
    int s = __ldg(g_rowstart + w), e = __ldg(g_rowstart + w + 1);
    const float4* x4 = (const float4*)g_x;
    float4 v = x4[(size_t)w * 32 + lane];
    float4 a1 = make_float4(0.f, 0.f, 0.f, 0.f);
    float4 a2 = make_float4(0.f, 0.f, 0.f, 0.f);
    float4 a3 = make_float4(0.f, 0.f, 0.f, 0.f);
    int i = s;
    for (; i + 3 < e; i += 4) {
        int s0 = __ldg(g_csr + i),     s1 = __ldg(g_csr + i + 1);
        int s2 = __ldg(g_csr + i + 2), s3 = __ldg(g_csr + i + 3);
        float4 u0 = x4[(size_t)s0 * 32 + lane];
        float4 u1 = x4[(size_t)s1 * 32 + lane];
        float4 u2 = x4[(size_t)s2 * 32 + lane];
        float4 u3 = x4[(size_t)s3 * 32 + lane];
        v.x += u0.x;  v.y += u0.y;  v.z += u0.z;  v.w += u0.w;
        a1.x += u1.x; a1.y += u1.y; a1.z += u1.z; a1.w += u1.w;
        a2.x += u2.x; a2.y += u2.y; a2.z += u2.z; a2.w += u2.w;
        a3.x += u3.x; a3.y += u3.y; a3.z += u3.z; a3.w += u3.w;
    }
    if (i + 1 < e) {
        int s0 = __ldg(g_csr + i), s1 = __ldg(g_csr + i + 1);
        float4 u0 = x4[(size_t)s0 * 32 + lane];
        float4 u1 = x4[(size_t)s1 * 32 + lane];
        v.x += u0.x;  v.y += u0.y;  v.z += u0.z;  v.w += u0.w;
        a1.x += u1.x; a1.y += u1.y; a1.z += u1.z; a1.w += u1.w;
        i += 2;
    }
    if (i < e) {
        int s0 = __ldg(g_csr + i);
        float4 u0 = x4[(size_t)s0 * 32 + lane];
        v.x += u0.x; v.y += u0.y; v.z += u0.z; v.w += u0.w;
    }
    v.x += a1.x + a2.x + a3.x;
    v.y += a1.y + a2.y + a3.y;
    v.z += a1.z + a2.z + a3.z;
    v.w += a1.w + a2.w + a3.w;

    __nv_bfloat16 h0 = __float2bfloat16(v.x), h1 = __float2bfloat16(v.y);
    __nv_bfloat16 h2 = __float2bfloat16(v.z), h3 = __float2bfloat16(v.w);
    __nv_bfloat16 l0 = __float2bfloat16(v.x - __bfloat162float(h0));
    __nv_bfloat16 l1 = __float2bfloat16(v.y - __bfloat162float(h1));
    __nv_bfloat16 l2 = __float2bfloat16(v.z - __bfloat162float(h2));
    __nv_bfloat16 l3 = __float2bfloat16(v.w - __bfloat162float(h3));
    size_t off = (size_t)w * HID + lane * 4;
    *(uint2*)(g_aggh + off) = make_uint2(pk(h0, h1), pk(h2, h3));
    *(uint2*)(g_aggl + off) = make_uint2(pk(l0, l1), pk(l2, l3));
}

// ---------------------------------------------------------------------------
// Weight prep: split W[k][c] -> transposed hi/lo images Wt[c][k], stride SA.
// ---------------------------------------------------------------------------
__global__ void prep_w(const float* __restrict__ W1, const float* __restrict__ W2) {
    int i = blockIdx.x * blockDim.x + threadIdx.x;
    if (i >= 2 * LAYERS * HID * HID) return;
    int which = i / (LAYERS * HID * HID);
    int r = i % (LAYERS * HID * HID);
    int l = r / (HID * HID);
    int kc = r % (HID * HID);
    int k = kc / HID, c = kc % HID;
    const float* W = which ? W2 : W1;
    float v = W[(size_t)l * HID * HID + k * HID + c];
    __nv_bfloat16 hi = __float2bfloat16(v);
    __nv_bfloat16 lo = __float2bfloat16(v - __bfloat162float(hi));
    size_t img = (size_t)which * LAYERS + l;
    size_t o = img * HID * SA + (size_t)c * SA + k;
    g_wt[o] = hi;
    g_wt[(size_t)2 * LAYERS * HID * SA + o] = lo;
}

// ---------------------------------------------------------------------------
// Persistent fused GIN MLP (R7 champion structure).
// smem: [W1h][W1l][W2h][W2l] (4 x 34816) + A bufs [2][hi 17408 | lo 17408]
// ---------------------------------------------------------------------------
#define WTILE_B   (HID * SA * 2)          // 34816
#define AHALF_B   (NODES_PT * SA * 2)     // 17408
#define ABUF_B    (2 * AHALF_B)           // 34816
#define SMEM_BYTES (4 * WTILE_B + 2 * ABUF_B)  // 208896

__device__ __forceinline__ void prefetch_tile(uint32_t dstbase, int node0, int tid) {
#pragma unroll
    for (int c = tid; c < 2048; c += 256) {
        int half = c >> 10;                 // 0: hi, 1: lo
        int r = (c & 1023) >> 4;
        int o = c & 15;
        const __nv_bfloat16* src =
            (half ? g_aggl : g_aggh) + ((size_t)(node0 + r) << 7) + (o << 3);
        uint32_t dst = dstbase + half * AHALF_B + r * (SA * 2) + o * 16;
        CP16(dst, src);
    }
}

// 3-product split GEMM over a 32x32 warp tile.
__device__ __forceinline__ void gemm_warp(
    uint32_t aAhi, uint32_t aAlo, uint32_t aWh, uint32_t aWl,
    int m0, int n0, int arow_off, int akoff, int brow_off, int bkoff,
    float (&acc)[2][4][4])
{
#pragma unroll
    for (int kb = 0; kb < HID; kb += 16) {
        uint32_t ah[2][4], al[2][4];
#pragma unroll
        for (int s = 0; s < 2; s++) {
            uint32_t ro = (uint32_t)((m0 + s * 16 + arow_off) * SA + kb + akoff) * 2;
            ldm_x4(ah[s], aAhi + ro);
            ldm_x4(al[s], aAlo + ro);
        }
#pragma unroll
        for (int nb = 0; nb < 2; nb++) {
            uint32_t bh[4], bl[4];
            uint32_t ro = (uint32_t)((n0 + nb * 16 + brow_off) * SA + kb + bkoff) * 2;
            ldm_x4(bh, aWh + ro);
            ldm_x4(bl, aWl + ro);
#pragma unroll
            for (int s = 0; s < 2; s++) {
                mma16816(acc[s][2 * nb],     ah[s], bh[0], bh[1]);
                mma16816(acc[s][2 * nb],     ah[s], bl[0], bl[1]);
                mma16816(acc[s][2 * nb],     al[s], bh[0], bh[1]);
                mma16816(acc[s][2 * nb + 1], ah[s], bh[2], bh[3]);
                mma16816(acc[s][2 * nb + 1], ah[s], bl[2], bl[3]);
                mma16816(acc[s][2 * nb + 1], al[s], bh[2], bh[3]);
            }
        }
    }
}

__global__ void __launch_bounds__(256, 1) mlp_mma(
    const float* __restrict__ b1, const float* __restrict__ b2, int l)
{
    extern __shared__ __align__(16) char S[];
    uint32_t base = smem_u32(S);
    uint32_t aW1h = base, aW1l = base + WTILE_B;
    uint32_t aW2h = base + 2 * WTILE_B, aW2l = base + 3 * WTILE_B;
    uint32_t aBuf[2] = { base + 4 * WTILE_B, base + 4 * WTILE_B + ABUF_B };
    char* pBuf[2] = { S + 4 * WTILE_B, S + 4 * WTILE_B + ABUF_B };

    int tid = threadIdx.x, warp = tid >> 5, lane = tid & 31;

    // ---- stage all weights once ----
    {
        const size_t istr = (size_t)HID * SA;
        const size_t lstr = (size_t)2 * LAYERS * HID * SA;
        const float4* srcs[4] = {
            (const float4*)(g_wt + (size_t)l * istr),
            (const float4*)(g_wt + lstr + (size_t)l * istr),
            (const float4*)(g_wt + (size_t)(LAYERS + l) * istr),
            (const float4*)(g_wt + lstr + (size_t)(LAYERS + l) * istr) };
#pragma unroll
        for (int q = 0; q < 4; q++) {
            float4* d = (float4*)(S + q * WTILE_B);
            for (int i = tid; i < WTILE_B / 16; i += 256) d[i] = srcs[q][i];
        }
    }

    // warp tiling: 8 warps -> (2 m) x (4 n); warp tile 32x32
    int m0 = (warp >> 2) * 32;
    int n0 = (warp & 3) * 32;
    int g = lane >> 3;
    int arow_off = (lane & 7) + ((g & 1) << 3);
    int akoff    = (g >> 1) << 3;
    int brow_off = (lane & 7) + ((g >> 1) << 3);
    int bkoff    = (g & 1) << 3;

    // hoist biases (columns fixed per warp across tiles)
    float b1v[4][2], b2v[4][2];
#pragma unroll
    for (int j = 0; j < 4; j++) {
        int col = n0 + j * 8 + (lane & 3) * 2;
        b1v[j][0] = __ldg(b1 + col); b1v[j][1] = __ldg(b1 + col + 1);
        b2v[j][0] = __ldg(b2 + col); b2v[j][1] = __ldg(b2 + col + 1);
    }

    int bid = blockIdx.x;
    prefetch_tile(aBuf[0], bid * NODES_PT, tid);
    CP_COMMIT();
    __syncthreads();   // weights staged

    int it = 0;
    for (int t = bid; t < NT; t += NBLK, it++) {
        int cur = it & 1;
        int node0 = t * NODES_PT;
        int tn = t + NBLK;
        if (tn < NT) {
            prefetch_tile(aBuf[1 - cur], tn * NODES_PT, tid);
            CP_COMMIT();
            CP_WAIT(1);
        } else {
            CP_WAIT(0);
        }
        __syncthreads();   // tile t resident

        uint32_t aAhi = aBuf[cur], aAlo = aBuf[cur] + AHALF_B;
        char* pA = pBuf[cur];

        float acc[2][4][4];
#pragma unroll
        for (int s = 0; s < 2; s++)
#pragma unroll
            for (int j = 0; j < 4; j++)
#pragma unroll
                for (int c = 0; c < 4; c++) acc[s][j][c] = 0.f;

        // ---- GEMM 1 ----
        gemm_warp(aAhi, aAlo, aW1h, aW1l, m0, n0,
                  arow_off, akoff, brow_off, bkoff, acc);
        __syncthreads();   // everyone done reading A before overwrite

        // ---- epilogue 1: h = relu(acc + b1) -> A buf (hi/lo) ----
        {
            int r0 = m0 + (lane >> 2);
#pragma unroll
            for (int j = 0; j < 4; j++) {
                int col = n0 + j * 8 + (lane & 3) * 2;
#pragma unroll
                for (int s = 0; s < 2; s++) {
                    int rA = r0 + s * 16, rB = rA + 8;
                    float v0 = fmaxf(acc[s][j][0] + b1v[j][0], 0.f);
                    float v1 = fmaxf(acc[s][j][1] + b1v[j][1], 0.f);
                    float v2 = fmaxf(acc[s][j][2] + b1v[j][0], 0.f);
                    float v3 = fmaxf(acc[s][j][3] + b1v[j][1], 0.f);
                    __nv_bfloat16 h0 = __float2bfloat16(v0), h1 = __float2bfloat16(v1);
                    __nv_bfloat16 h2 = __float2bfloat16(v2), h3 = __float2bfloat16(v3);
                    __nv_bfloat16 q0 = __float2bfloat16(v0 - __bfloat162float(h0));
                    __nv_bfloat16 q1 = __float2bfloat16(v1 - __bfloat162float(h1));
                    __nv_bfloat16 q2 = __float2bfloat16(v2 - __bfloat162float(h2));
                    __nv_bfloat16 q3 = __float2bfloat16(v3 - __bfloat162float(h3));
                    uint32_t oA = (uint32_t)(rA * SA + col) * 2;
                    uint32_t oB = (uint32_t)(rB * SA + col) * 2;
                    *(uint32_t*)(pA + oA) = pk(h0, h1);
                    *(uint32_t*)(pA + AHALF_B + oA) = pk(q0, q1);
                    *(uint32_t*)(pA + oB) = pk(h2, h3);
                    *(uint32_t*)(pA + AHALF_B + oB) = pk(q2, q3);
                }
            }
        }
        __syncthreads();

#pragma unroll
        for (int s = 0; s < 2; s++)
#pragma unroll
            for (int j = 0; j < 4; j++)
#pragma unroll
                for (int c = 0; c < 4; c++) acc[s][j][c] = 0.f;

        // ---- GEMM 2 ----
        gemm_warp(aAhi, aAlo, aW2h, aW2l, m0, n0,
                  arow_off, akoff, brow_off, bkoff, acc);

        // ---- epilogue 2: relu(acc + b2) -> g_x directly ----
        {
            int r0 = m0 + (lane >> 2);
#pragma unroll
            for (int j = 0; j < 4; j++) {
                int col = n0 + j * 8 + (lane & 3) * 2;
#pragma unroll
                for (int s = 0; s < 2; s++) {
                    int rA = r0 + s * 16, rB = rA + 8;
                    int gA = node0 + rA, gB = node0 + rB;
                    if (gA < N_NODES) {
                        float2 v = make_float2(fmaxf(acc[s][j][0] + b2v[j][0], 0.f),
                                               fmaxf(acc[s][j][1] + b2v[j][1], 0.f));
                        *(float2*)(g_x + (size_t)gA * HID + col) = v;
                    }
                    if (gB < N_NODES) {
                        float2 v = make_float2(fmaxf(acc[s][j][2] + b2v[j][0], 0.f),
                                               fmaxf(acc[s][j][3] + b2v[j][1], 0.f));
                        *(float2*)(g_x + (size_t)gB * HID + col) = v;
                    }
                }
            }
        }
        __syncthreads();   // A buf fully read before next prefetch overwrites
    }
}

// ---------------------------------------------------------------------------
// Global mean pool
// ---------------------------------------------------------------------------
__global__ void pool_kernel(const int* __restrict__ batch,
                            float* __restrict__ out) {
    int g = blockIdx.x;
    __shared__ int s_range[2];
    if (threadIdx.x == 0) {
        int lo = 0, hi = N_NODES;
        while (lo < hi) { int m = (lo + hi) >> 1; if (batch[m] < g) lo = m + 1; else hi = m; }
        s_range[0] = lo;
        lo = 0; hi = N_NODES;
        while (lo < hi) { int m = (lo + hi) >> 1; if (batch[m] < g + 1) lo = m + 1; else hi = m; }
        s_range[1] = lo;
    }
    __syncthreads();
    int start = s_range[0], end = s_range[1];
    float sum = 0.f;
    for (int n = start; n < end; n++)
        sum += g_x[(size_t)n * HID + threadIdx.x];
    float cnt = (float)(end - start);
    out[g * HID + threadIdx.x] = sum / fmaxf(cnt, 1.0f);
}

// ---------------------------------------------------------------------------
// Inputs: x_tokens, edge_index, batch, emb, W1, b1, W2, b2
// ---------------------------------------------------------------------------
extern "C" void kernel_launch(void* const* d_in, const int* in_sizes, int n_in,
                              void* d_out, int out_size) {
    const int*   tok   = (const int*)  d_in[0];
    const int*   ei    = (const int*)  d_in[1];
    const int*   batch = (const int*)  d_in[2];
    const float* emb   = (const float*)d_in[3];
    const float* W1    = (const float*)d_in[4];
    const float* b1    = (const float*)d_in[5];
    const float* W2    = (const float*)d_in[6];
    const float* b2    = (const float*)d_in[7];
    float* out = (float*)d_out;

    cudaFuncSetAttribute(mlp_mma, cudaFuncAttributeMaxDynamicSharedMemorySize,
                         SMEM_BYTES);

    prep_w<<<(2 * LAYERS * HID * HID + 255) / 256, 256>>>(W1, W2);
    embed_kernel<<<(N_NODES * 32 + 255) / 256, 256>>>(tok, emb);

    k_hist <<<(N_EDGES + 255) / 256, 256>>>(ei);
    k_scan1<<<SCAN_NB, SCAN_B>>>();
    k_scan2<<<1, 32>>>();
    k_scan3<<<(N_NODES + 255) / 256, 256>>>();
    k_fill <<<(N_EDGES + 255) / 256, 256>>>(ei);

    for (int l = 0; l < LAYERS; l++) {
        gather_kernel<<<(N_NODES * 32 + 255) / 256, 256>>>();
        mlp_mma<<<NBLK, 256, SMEM_BYTES>>>(
            b1 + (size_t)l * HID, b2 + (size_t)l * HID, l);
    }

    pool_kernel<<<N_GRAPHS, HID>>>(batch, out);
}

// round 13
// speedup vs baseline: 2.2611x; 1.0001x over previous
#include <cuda_runtime.h>
#include <cuda_bf16.h>
#include <cstdint>

#define N_NODES  100000
#define N_PAD    100096            // 1564 * 64
#define N_EDGES  600000
#define N_GRAPHS 2000
#define HID      128
#define LAYERS   6
#define SA       136               // bf16 row stride in smem (272 B)
#define NODES_PT 64                // nodes per tile
#define NT       (N_PAD / NODES_PT)  // 1564 tiles
#define NBLK     148
#define NTHREADS 512               // 16 warps
#define SCAN_B   1024
#define SCAN_NB  ((N_NODES + SCAN_B - 1) / SCAN_B)

// ---------------------------------------------------------------------------
// Persistent scratch (allocation-free)
// ---------------------------------------------------------------------------
__device__ float g_x[(size_t)N_NODES * HID];
__device__ __align__(16) __nv_bfloat16 g_aggh[(size_t)N_PAD * HID];  // pad rows stay 0
__device__ __align__(16) __nv_bfloat16 g_aggl[(size_t)N_PAD * HID];
__device__ __align__(16) __nv_bfloat16 g_wt[(size_t)2 * 2 * LAYERS * HID * SA];
// CSR scratch
__device__ int g_deg[N_NODES];
__device__ int g_rowstart[N_NODES + 1];
__device__ int g_cursor[N_NODES];
__device__ int g_blocksum[SCAN_NB];
__device__ int g_csr[N_EDGES];

// ---------------------------------------------------------------------------
// helpers
// ---------------------------------------------------------------------------
__device__ __forceinline__ uint32_t smem_u32(const void* p) {
    uint32_t a;
    asm("{ .reg .u64 t; cvta.to.shared.u64 t, %1; cvt.u32.u64 %0, t; }"
        : "=r"(a) : "l"(p));
    return a;
}
__device__ __forceinline__ void ldm_x4(uint32_t (&r)[4], uint32_t addr) {
    asm volatile("ldmatrix.sync.aligned.m8n8.x4.shared.b16 {%0,%1,%2,%3}, [%4];"
                 : "=r"(r[0]), "=r"(r[1]), "=r"(r[2]), "=r"(r[3]) : "r"(addr));
}
__device__ __forceinline__ void mma16816(float (&d)[4], const uint32_t (&a)[4],
                                         uint32_t b0, uint32_t b1) {
    asm volatile(
        "mma.sync.aligned.m16n8k16.row.col.f32.bf16.bf16.f32 "
        "{%0,%1,%2,%3}, {%4,%5,%6,%7}, {%8,%9}, {%0,%1,%2,%3};"
        : "+f"(d[0]), "+f"(d[1]), "+f"(d[2]), "+f"(d[3])
        : "r"(a[0]), "r"(a[1]), "r"(a[2]), "r"(a[3]), "r"(b0), "r"(b1));
}
__device__ __forceinline__ uint32_t pk(__nv_bfloat16 a, __nv_bfloat16 b) {
    return (uint32_t)__bfloat16_as_ushort(a) |
           ((uint32_t)__bfloat16_as_ushort(b) << 16);
}
#define CP16(dst, src) \
    asm volatile("cp.async.cg.shared.global [%0], [%1], 16;" \
                 :: "r"(dst), "l"(src) : "memory")
#define CP_COMMIT()  asm volatile("cp.async.commit_group;" ::: "memory")
#define CP_WAIT(n)   asm volatile("cp.async.wait_group %0;" :: "n"(n) : "memory")

// ---------------------------------------------------------------------------
// Embedding lookup (also zeroes g_deg, saving a launch)
// ---------------------------------------------------------------------------
__global__ void embed_kernel(const int* __restrict__ tok,
                             const float* __restrict__ emb) {
    int i = blockIdx.x * blockDim.x + threadIdx.x;
    if (i >= N_NODES * 32) return;
    if (i < N_NODES) g_deg[i] = 0;
    int node = i >> 5, d = i & 31;
    ((float4*)g_x)[i] = ((const float4*)emb)[tok[node] * 32 + d];
}

// ---------------------------------------------------------------------------
// CSR build
// ---------------------------------------------------------------------------
__global__ void k_hist(const int* __restrict__ ei) {
    int i = blockIdx.x * blockDim.x + threadIdx.x;
    if (i < N_EDGES) atomicAdd(&g_deg[ei[N_EDGES + i]], 1);
}
__global__ void k_scan1() {
    __shared__ int sm[SCAN_B];
    int tid = threadIdx.x;
    int i = blockIdx.x * SCAN_B + tid;
    int v = (i < N_NODES) ? g_deg[i] : 0;
    sm[tid] = v;
    __syncthreads();
#pragma unroll
    for (int o = 1; o < SCAN_B; o <<= 1) {
        int t = (tid >= o) ? sm[tid - o] : 0;
        __syncthreads();
        sm[tid] += t;
        __syncthreads();
    }
    if (i < N_NODES) g_rowstart[i] = sm[tid] - v;
    if (tid == SCAN_B - 1) g_blocksum[blockIdx.x] = sm[tid];
}
__global__ void k_scan2() {
    if (threadIdx.x == 0) {
        int run = 0;
        for (int b = 0; b < SCAN_NB; b++) {
            int t = g_blocksum[b];
            g_blocksum[b] = run;
            run += t;
        }
        g_rowstart[N_NODES] = run;
    }
}
__global__ void k_scan3() {
    int i = blockIdx.x * blockDim.x + threadIdx.x;
    if (i < N_NODES) {
        int r = g_rowstart[i] + g_blocksum[i / SCAN_B];
        g_rowstart[i] = r;
        g_cursor[i] = r;
    }
}
__global__ void k_fill(const int* __restrict__ ei) {
    int i = blockIdx.x * blockDim.x + threadIdx.x;
    if (i < N_EDGES) {
        int dst = ei[N_EDGES + i];
        g_csr[atomicAdd(&g_cursor[dst], 1)] = ei[i];
    }
}

// ---------------------------------------------------------------------------
// Gather: agg[n] = x[n] + sum_e x[csr[e]] (simple loop: LTS-bound, unroll
// proved neutral in R12). Writes pre-split bf16 hi/lo.
// ---------------------------------------------------------------------------
__global__ void gather_kernel() {
    int w = (blockIdx.x * blockDim.x + threadIdx.x) >> 5;
    int lane = threadIdx.x & 31;
    if (w >= N_NODES) return;
    int s = __ldg(g_rowstart + w), e = __ldg(g_rowstart + w + 1);
    const float4* x4 = (const float4*)g_x;
    float4 v = x4[(size_t)w * 32 + lane];
    for (int i = s; i < e; i++) {
        int src = __ldg(g_csr + i);
        float4 u = x4[(size_t)src * 32 + lane];
        v.x += u.x; v.y += u.y; v.z += u.z; v.w += u.w;
    }
    __nv_bfloat16 h0 = __float2bfloat16(v.x), h1 = __float2bfloat16(v.y);
    __nv_bfloat16 h2 = __float2bfloat16(v.z), h3 = __float2bfloat16(v.w);
    __nv_bfloat16 l0 = __float2bfloat16(v.x - __bfloat162float(h0));
    __nv_bfloat16 l1 = __float2bfloat16(v.y - __bfloat162float(h1));
    __nv_bfloat16 l2 = __float2bfloat16(v.z - __bfloat162float(h2));
    __nv_bfloat16 l3 = __float2bfloat16(v.w - __bfloat162float(h3));
    size_t off = (size_t)w * HID + lane * 4;
    *(uint2*)(g_aggh + off) = make_uint2(pk(h0, h1), pk(h2, h3));
    *(uint2*)(g_aggl + off) = make_uint2(pk(l0, l1), pk(l2, l3));
}

// ---------------------------------------------------------------------------
// Weight prep: split W[k][c] -> transposed hi/lo images Wt[c][k], stride SA.
// ---------------------------------------------------------------------------
__global__ void prep_w(const float* __restrict__ W1, const float* __restrict__ W2) {
    int i = blockIdx.x * blockDim.x + threadIdx.x;
    if (i >= 2 * LAYERS * HID * HID) return;
    int which = i / (LAYERS * HID * HID);
    int r = i % (LAYERS * HID * HID);
    int l = r / (HID * HID);
    int kc = r % (HID * HID);
    int k = kc / HID, c = kc % HID;
    const float* W = which ? W2 : W1;
    float v = W[(size_t)l * HID * HID + k * HID + c];
    __nv_bfloat16 hi = __float2bfloat16(v);
    __nv_bfloat16 lo = __float2bfloat16(v - __bfloat162float(hi));
    size_t img = (size_t)which * LAYERS + l;
    size_t o = img * HID * SA + (size_t)c * SA + k;
    g_wt[o] = hi;
    g_wt[(size_t)2 * LAYERS * HID * SA + o] = lo;
}

// ---------------------------------------------------------------------------
// Persistent fused GIN MLP, 16 warps (4m x 4n), warp tile 16x32.
// smem: [W1h][W1l][W2h][W2l] (4 x 34816) + A bufs [2][hi 17408 | lo 17408]
// ---------------------------------------------------------------------------
#define WTILE_B   (HID * SA * 2)          // 34816
#define AHALF_B   (NODES_PT * SA * 2)     // 17408
#define ABUF_B    (2 * AHALF_B)           // 34816
#define SMEM_BYTES (4 * WTILE_B + 2 * ABUF_B)  // 208896

__device__ __forceinline__ void prefetch_tile(uint32_t dstbase, int node0, int tid) {
#pragma unroll
    for (int c = tid; c < 2048; c += NTHREADS) {
        int half = c >> 10;                 // 0: hi, 1: lo
        int r = (c & 1023) >> 4;
        int o = c & 15;
        const __nv_bfloat16* src =
            (half ? g_aggl : g_aggh) + ((size_t)(node0 + r) << 7) + (o << 3);
        uint32_t dst = dstbase + half * AHALF_B + r * (SA * 2) + o * 16;
        CP16(dst, src);
    }
}

// 3-product split GEMM over a 16x32 warp tile.
__device__ __forceinline__ void gemm_warp(
    uint32_t aAhi, uint32_t aAlo, uint32_t aWh, uint32_t aWl,
    int m0, int n0, int arow_off, int akoff, int brow_off, int bkoff,
    float (&acc)[4][4])
{
#pragma unroll
    for (int kb = 0; kb < HID; kb += 16) {
        uint32_t ah[4], al[4];
        uint32_t aro = (uint32_t)((m0 + arow_off) * SA + kb + akoff) * 2;
        ldm_x4(ah, aAhi + aro);
        ldm_x4(al, aAlo + aro);
#pragma unroll
        for (int nb = 0; nb < 2; nb++) {
            uint32_t bh[4], bl[4];
            uint32_t ro = (uint32_t)((n0 + nb * 16 + brow_off) * SA + kb + bkoff) * 2;
            ldm_x4(bh, aWh + ro);
            ldm_x4(bl, aWl + ro);
            mma16816(acc[2 * nb],     ah, bh[0], bh[1]);
            mma16816(acc[2 * nb],     ah, bl[0], bl[1]);
            mma16816(acc[2 * nb],     al, bh[0], bh[1]);
            mma16816(acc[2 * nb + 1], ah, bh[2], bh[3]);
            mma16816(acc[2 * nb + 1], ah, bl[2], bl[3]);
            mma16816(acc[2 * nb + 1], al, bh[2], bh[3]);
        }
    }
}

__global__ void __launch_bounds__(NTHREADS, 1) mlp_mma(
    const float* __restrict__ b1, const float* __restrict__ b2, int l)
{
    extern __shared__ __align__(16) char S[];
    uint32_t base = smem_u32(S);
    uint32_t aW1h = base, aW1l = base + WTILE_B;
    uint32_t aW2h = base + 2 * WTILE_B, aW2l = base + 3 * WTILE_B;
    uint32_t aBuf[2] = { base + 4 * WTILE_B, base + 4 * WTILE_B + ABUF_B };
    char* pBuf[2] = { S + 4 * WTILE_B, S + 4 * WTILE_B + ABUF_B };

    int tid = threadIdx.x, warp = tid >> 5, lane = tid & 31;

    // ---- stage all weights once ----
    {
        const size_t istr = (size_t)HID * SA;
        const size_t lstr = (size_t)2 * LAYERS * HID * SA;
        const float4* srcs[4] = {
            (const float4*)(g_wt + (size_t)l * istr),
            (const float4*)(g_wt + lstr + (size_t)l * istr),
            (const float4*)(g_wt + (size_t)(LAYERS + l) * istr),
            (const float4*)(g_wt + lstr + (size_t)(LAYERS + l) * istr) };
#pragma unroll
        for (int q = 0; q < 4; q++) {
            float4* d = (float4*)(S + q * WTILE_B);
            for (int i = tid; i < WTILE_B / 16; i += NTHREADS) d[i] = srcs[q][i];
        }
    }

    // warp tiling: 16 warps -> (4 m) x (4 n); warp tile 16x32
    int m0 = (warp >> 2) * 16;
    int n0 = (warp & 3) * 32;
    int g = lane >> 3;
    int arow_off = (lane & 7) + ((g & 1) << 3);
    int akoff    = (g >> 1) << 3;
    int brow_off = (lane & 7) + ((g >> 1) << 3);
    int bkoff    = (g & 1) << 3;

    // hoist biases (columns fixed per warp across tiles)
    float b1v[4][2], b2v[4][2];
#pragma unroll
    for (int j = 0; j < 4; j++) {
        int col = n0 + j * 8 + (lane & 3) * 2;
        b1v[j][0] = __ldg(b1 + col); b1v[j][1] = __ldg(b1 + col + 1);
        b2v[j][0] = __ldg(b2 + col); b2v[j][1] = __ldg(b2 + col + 1);
    }

    int bid = blockIdx.x;
    prefetch_tile(aBuf[0], bid * NODES_PT, tid);
    CP_COMMIT();
    __syncthreads();   // weights staged

    int it = 0;
    for (int t = bid; t < NT; t += NBLK, it++) {
        int cur = it & 1;
        int node0 = t * NODES_PT;
        int tn = t + NBLK;
        if (tn < NT) {
            prefetch_tile(aBuf[1 - cur], tn * NODES_PT, tid);
            CP_COMMIT();
            CP_WAIT(1);
        } else {
            CP_WAIT(0);
        }
        __syncthreads();   // tile t resident

        uint32_t aAhi = aBuf[cur], aAlo = aBuf[cur] + AHALF_B;
        char* pA = pBuf[cur];

        float acc[4][4];
#pragma unroll
        for (int j = 0; j < 4; j++)
#pragma unroll
            for (int c = 0; c < 4; c++) acc[j][c] = 0.f;

        // ---- GEMM 1 ----
        gemm_warp(aAhi, aAlo, aW1h, aW1l, m0, n0,
                  arow_off, akoff, brow_off, bkoff, acc);
        __syncthreads();   // everyone done reading A before overwrite

        // ---- epilogue 1: h = relu(acc + b1) -> A buf (hi/lo) ----
        {
            int rA = m0 + (lane >> 2), rB = rA + 8;
#pragma unroll
            for (int j = 0; j < 4; j++) {
                int col = n0 + j * 8 + (lane & 3) * 2;
                float v0 = fmaxf(acc[j][0] + b1v[j][0], 0.f);
                float v1 = fmaxf(acc[j][1] + b1v[j][1], 0.f);
                float v2 = fmaxf(acc[j][2] + b1v[j][0], 0.f);
                float v3 = fmaxf(acc[j][3] + b1v[j][1], 0.f);
                __nv_bfloat16 h0 = __float2bfloat16(v0), h1 = __float2bfloat16(v1);
                __nv_bfloat16 h2 = __float2bfloat16(v2), h3 = __float2bfloat16(v3);
                __nv_bfloat16 q0 = __float2bfloat16(v0 - __bfloat162float(h0));
                __nv_bfloat16 q1 = __float2bfloat16(v1 - __bfloat162float(h1));
                __nv_bfloat16 q2 = __float2bfloat16(v2 - __bfloat162float(h2));
                __nv_bfloat16 q3 = __float2bfloat16(v3 - __bfloat162float(h3));
                uint32_t oA = (uint32_t)(rA * SA + col) * 2;
                uint32_t oB = (uint32_t)(rB * SA + col) * 2;
                *(uint32_t*)(pA + oA) = pk(h0, h1);
                *(uint32_t*)(pA + AHALF_B + oA) = pk(q0, q1);
                *(uint32_t*)(pA + oB) = pk(h2, h3);
                *(uint32_t*)(pA + AHALF_B + oB) = pk(q2, q3);
            }
        }
        __syncthreads();

#pragma unroll
        for (int j = 0; j < 4; j++)
#pragma unroll
            for (int c = 0; c < 4; c++) acc[j][c] = 0.f;

        // ---- GEMM 2 ----
        gemm_warp(aAhi, aAlo, aW2h, aW2l, m0, n0,
                  arow_off, akoff, brow_off, bkoff, acc);

        // ---- epilogue 2: relu(acc + b2) -> g_x directly ----
        {
            int rA = m0 + (lane >> 2), rB = rA + 8;
            int gA = node0 + rA, gB = node0 + rB;
#pragma unroll
            for (int j = 0; j < 4; j++) {
                int col = n0 + j * 8 + (lane & 3) * 2;
                if (gA < N_NODES) {
                    float2 v = make_float2(fmaxf(acc[j][0] + b2v[j][0], 0.f),
                                           fmaxf(acc[j][1] + b2v[j][1], 0.f));
                    *(float2*)(g_x + (size_t)gA * HID + col) = v;
                }
                if (gB < N_NODES) {
                    float2 v = make_float2(fmaxf(acc[j][2] + b2v[j][0], 0.f),
                                           fmaxf(acc[j][3] + b2v[j][1], 0.f));
                    *(float2*)(g_x + (size_t)gB * HID + col) = v;
                }
            }
        }
        __syncthreads();   // A buf fully read before next prefetch overwrites
    }
}

// ---------------------------------------------------------------------------
// Global mean pool
// ---------------------------------------------------------------------------
__global__ void pool_kernel(const int* __restrict__ batch,
                            float* __restrict__ out) {
    int g = blockIdx.x;
    __shared__ int s_range[2];
    if (threadIdx.x == 0) {
        int lo = 0, hi = N_NODES;
        while (lo < hi) { int m = (lo + hi) >> 1; if (batch[m] < g) lo = m + 1; else hi = m; }
        s_range[0] = lo;
        lo = 0; hi = N_NODES;
        while (lo < hi) { int m = (lo + hi) >> 1; if (batch[m] < g + 1) lo = m + 1; else hi = m; }
        s_range[1] = lo;
    }
    __syncthreads();
    int start = s_range[0], end = s_range[1];
    float sum = 0.f;
    for (int n = start; n < end; n++)
        sum += g_x[(size_t)n * HID + threadIdx.x];
    float cnt = (float)(end - start);
    out[g * HID + threadIdx.x] = sum / fmaxf(cnt, 1.0f);
}

// ---------------------------------------------------------------------------
// Inputs: x_tokens, edge_index, batch, emb, W1, b1, W2, b2
// ---------------------------------------------------------------------------
extern "C" void kernel_launch(void* const* d_in, const int* in_sizes, int n_in,
                              void* d_out, int out_size) {
    const int*   tok   = (const int*)  d_in[0];
    const int*   ei    = (const int*)  d_in[1];
    const int*   batch = (const int*)  d_in[2];
    const float* emb   = (const float*)d_in[3];
    const float* W1    = (const float*)d_in[4];
    const float* b1    = (const float*)d_in[5];
    const float* W2    = (const float*)d_in[6];
    const float* b2    = (const float*)d_in[7];
    float* out = (float*)d_out;

    cudaFuncSetAttribute(mlp_mma, cudaFuncAttributeMaxDynamicSharedMemorySize,
                         SMEM_BYTES);

    prep_w<<<(2 * LAYERS * HID * HID + 255) / 256, 256>>>(W1, W2);
    embed_kernel<<<(N_NODES * 32 + 255) / 256, 256>>>(tok, emb);

    k_hist <<<(N_EDGES + 255) / 256, 256>>>(ei);
    k_scan1<<<SCAN_NB, SCAN_B>>>();
    k_scan2<<<1, 32>>>();
    k_scan3<<<(N_NODES + 255) / 256, 256>>>();
    k_fill <<<(N_EDGES + 255) / 256, 256>>>(ei);

    for (int l = 0; l < LAYERS; l++) {
        gather_kernel<<<(N_NODES * 32 + 255) / 256, 256>>>();
        mlp_mma<<<NBLK, 256 * 2, SMEM_BYTES>>>(
            b1 + (size_t)l * HID, b2 + (size_t)l * HID, l);
    }

    pool_kernel<<<N_GRAPHS, HID>>>(batch, out);
}

// round 14
// speedup vs baseline: 2.6767x; 1.1838x over previous
#include <cuda_runtime.h>
#include <cuda_bf16.h>
#include <cstdint>

#define N_NODES  100000
#define N_PAD    100096            // 782 * 128
#define N_EDGES  600000
#define N_GRAPHS 2000
#define HID      128
#define LAYERS   6
#define SA       136               // bf16 row stride in smem (272 B)
#define NODES_PT 128               // nodes per tile (8 warps x 16 rows)
#define NT       (N_PAD / NODES_PT)  // 782 tiles
#define NBLK     148
#define SCAN_B   1024
#define SCAN_NB  ((N_NODES + SCAN_B - 1) / SCAN_B)

// ---------------------------------------------------------------------------
// Persistent scratch (allocation-free)
// ---------------------------------------------------------------------------
__device__ float g_x[(size_t)N_NODES * HID];
__device__ __align__(16) __nv_bfloat16 g_aggh[(size_t)N_PAD * HID];
__device__ __align__(16) __nv_bfloat16 g_aggl[(size_t)N_PAD * HID];
__device__ __align__(16) __nv_bfloat16 g_wt[(size_t)2 * 2 * LAYERS * HID * SA];
// CSR scratch
__device__ int g_deg[N_NODES];
__device__ int g_rowstart[N_NODES + 1];
__device__ int g_cursor[N_NODES];
__device__ int g_blocksum[SCAN_NB];
__device__ int g_csr[N_EDGES];

// ---------------------------------------------------------------------------
// helpers
// ---------------------------------------------------------------------------
__device__ __forceinline__ uint32_t smem_u32(const void* p) {
    uint32_t a;
    asm("{ .reg .u64 t; cvta.to.shared.u64 t, %1; cvt.u32.u64 %0, t; }"
        : "=r"(a) : "l"(p));
    return a;
}
__device__ __forceinline__ void ldm_x4(uint32_t (&r)[4], uint32_t addr) {
    asm volatile("ldmatrix.sync.aligned.m8n8.x4.shared.b16 {%0,%1,%2,%3}, [%4];"
                 : "=r"(r[0]), "=r"(r[1]), "=r"(r[2]), "=r"(r[3]) : "r"(addr));
}
__device__ __forceinline__ void mma16816(float (&d)[4], const uint32_t (&a)[4],
                                         uint32_t b0, uint32_t b1) {
    asm volatile(
        "mma.sync.aligned.m16n8k16.row.col.f32.bf16.bf16.f32 "
        "{%0,%1,%2,%3}, {%4,%5,%6,%7}, {%8,%9}, {%0,%1,%2,%3};"
        : "+f"(d[0]), "+f"(d[1]), "+f"(d[2]), "+f"(d[3])
        : "r"(a[0]), "r"(a[1]), "r"(a[2]), "r"(a[3]), "r"(b0), "r"(b1));
}
__device__ __forceinline__ uint32_t pk(__nv_bfloat16 a, __nv_bfloat16 b) {
    return (uint32_t)__bfloat16_as_ushort(a) |
           ((uint32_t)__bfloat16_as_ushort(b) << 16);
}
#define CP16(dst, src) \
    asm volatile("cp.async.cg.shared.global [%0], [%1], 16;" \
                 :: "r"(dst), "l"(src) : "memory")
#define CP_COMMIT()  asm volatile("cp.async.commit_group;" ::: "memory")
#define CP_WAIT(n)   asm volatile("cp.async.wait_group %0;" :: "n"(n) : "memory")

// ---------------------------------------------------------------------------
// Embedding lookup (also zeroes g_deg, saving a launch)
// ---------------------------------------------------------------------------
__global__ void embed_kernel(const int* __restrict__ tok,
                             const float* __restrict__ emb) {
    int i = blockIdx.x * blockDim.x + threadIdx.x;
    if (i >= N_NODES * 32) return;
    if (i < N_NODES) g_deg[i] = 0;
    int node = i >> 5, d = i & 31;
    ((float4*)g_x)[i] = ((const float4*)emb)[tok[node] * 32 + d];
}

// ---------------------------------------------------------------------------
// CSR build
// ---------------------------------------------------------------------------
__global__ void k_hist(const int* __restrict__ ei) {
    int i = blockIdx.x * blockDim.x + threadIdx.x;
    if (i < N_EDGES) atomicAdd(&g_deg[ei[N_EDGES + i]], 1);
}
__global__ void k_scan1() {
    __shared__ int sm[SCAN_B];
    int tid = threadIdx.x;
    int i = blockIdx.x * SCAN_B + tid;
    int v = (i < N_NODES) ? g_deg[i] : 0;
    sm[tid] = v;
    __syncthreads();
#pragma unroll
    for (int o = 1; o < SCAN_B; o <<= 1) {
        int t = (tid >= o) ? sm[tid - o] : 0;
        __syncthreads();
        sm[tid] += t;
        __syncthreads();
    }
    if (i < N_NODES) g_rowstart[i] = sm[tid] - v;
    if (tid == SCAN_B - 1) g_blocksum[blockIdx.x] = sm[tid];
}
__global__ void k_scan2() {
    if (threadIdx.x == 0) {
        int run = 0;
        for (int b = 0; b < SCAN_NB; b++) {
            int t = g_blocksum[b];
            g_blocksum[b] = run;
            run += t;
        }
        g_rowstart[N_NODES] = run;
    }
}
__global__ void k_scan3() {
    int i = blockIdx.x * blockDim.x + threadIdx.x;
    if (i < N_NODES) {
        int r = g_rowstart[i] + g_blocksum[i / SCAN_B];
        g_rowstart[i] = r;
        g_cursor[i] = r;
    }
}
__global__ void k_fill(const int* __restrict__ ei) {
    int i = blockIdx.x * blockDim.x + threadIdx.x;
    if (i < N_EDGES) {
        int dst = ei[N_EDGES + i];
        g_csr[atomicAdd(&g_cursor[dst], 1)] = ei[i];
    }
}

// ---------------------------------------------------------------------------
// Gather: agg[n] = x[n] + sum_e x[csr[e]]  (simple loop: LTS-bound)
// Writes pre-split bf16 hi/lo.
// ---------------------------------------------------------------------------
__global__ void gather_kernel() {
    int w = (blockIdx.x * blockDim.x + threadIdx.x) >> 5;
    int lane = threadIdx.x & 31;
    if (w >= N_NODES) return;
    int s = __ldg(g_rowstart + w), e = __ldg(g_rowstart + w + 1);
    const float4* x4 = (const float4*)g_x;
    float4 v = x4[(size_t)w * 32 + lane];
    for (int i = s; i < e; i++) {
        int src = __ldg(g_csr + i);
        float4 u = x4[(size_t)src * 32 + lane];
        v.x += u.x; v.y += u.y; v.z += u.z; v.w += u.w;
    }
    __nv_bfloat16 h0 = __float2bfloat16(v.x), h1 = __float2bfloat16(v.y);
    __nv_bfloat16 h2 = __float2bfloat16(v.z), h3 = __float2bfloat16(v.w);
    __nv_bfloat16 l0 = __float2bfloat16(v.x - __bfloat162float(h0));
    __nv_bfloat16 l1 = __float2bfloat16(v.y - __bfloat162float(h1));
    __nv_bfloat16 l2 = __float2bfloat16(v.z - __bfloat162float(h2));
    __nv_bfloat16 l3 = __float2bfloat16(v.w - __bfloat162float(h3));
    size_t off = (size_t)w * HID + lane * 4;
    *(uint2*)(g_aggh + off) = make_uint2(pk(h0, h1), pk(h2, h3));
    *(uint2*)(g_aggl + off) = make_uint2(pk(l0, l1), pk(l2, l3));
}

// ---------------------------------------------------------------------------
// Weight prep: split W[k][c] -> transposed hi/lo images Wt[c][k], stride SA.
// ---------------------------------------------------------------------------
__global__ void prep_w(const float* __restrict__ W1, const float* __restrict__ W2) {
    int i = blockIdx.x * blockDim.x + threadIdx.x;
    if (i >= 2 * LAYERS * HID * HID) return;
    int which = i / (LAYERS * HID * HID);
    int r = i % (LAYERS * HID * HID);
    int l = r / (HID * HID);
    int kc = r % (HID * HID);
    int k = kc / HID, c = kc % HID;
    const float* W = which ? W2 : W1;
    float v = W[(size_t)l * HID * HID + k * HID + c];
    __nv_bfloat16 hi = __float2bfloat16(v);
    __nv_bfloat16 lo = __float2bfloat16(v - __bfloat162float(hi));
    size_t img = (size_t)which * LAYERS + l;
    size_t o = img * HID * SA + (size_t)c * SA + k;
    g_wt[o] = hi;
    g_wt[(size_t)2 * LAYERS * HID * SA + o] = lo;
}

// ---------------------------------------------------------------------------
// Persistent register-fused GIN MLP: 8 warps, warp tile 16 rows x 128 cols.
// GEMM1 accumulators stay in registers, become GEMM2's A fragments
// (two adjacent 8-col C tiles == one k16 A fragment, lane-for-lane).
// Warp-private A rows + warp-private cp.async => NO per-tile block barriers.
// smem: W1h W1l W2h W2l (4x34816) + A buf hi/lo (2x34816) + biases (1KB)
// ---------------------------------------------------------------------------
#define WTILE_B   (HID * SA * 2)            // 34816
#define AHALF_B   (NODES_PT * SA * 2)       // 34816 (128 rows)
#define BIAS_OFF  (4 * WTILE_B + 2 * AHALF_B)   // 208896
#define SMEM_BYTES (BIAS_OFF + 1024)            // 209920

// warp-private prefetch of this warp's 16 rows (hi+lo), 16 cp.16B per lane
__device__ __forceinline__ void prefetch_rows(uint32_t aA, int m0, int gnode0,
                                              int lane) {
#pragma unroll
    for (int i = 0; i < 16; i++) {
        int c = lane + 32 * i;        // 0..511
        int half = c >> 8;            // 0:hi 1:lo
        int r = (c >> 4) & 15;
        int o = c & 15;
        const __nv_bfloat16* src =
            (half ? g_aggl : g_aggh) + ((size_t)(gnode0 + r) << 7) + (o << 3);
        uint32_t dst = aA + half * AHALF_B + (m0 + r) * (SA * 2) + o * 16;
        CP16(dst, src);
    }
}

__global__ void __launch_bounds__(256, 1) mlp_mma(
    const float* __restrict__ b1, const float* __restrict__ b2, int l)
{
    extern __shared__ __align__(16) char S[];
    uint32_t base = smem_u32(S);
    uint32_t aW1h = base, aW1l = base + WTILE_B;
    uint32_t aW2h = base + 2 * WTILE_B, aW2l = base + 3 * WTILE_B;
    uint32_t aA = base + 4 * WTILE_B;      // hi; lo at +AHALF_B
    float* sbias = (float*)(S + BIAS_OFF); // [0:128) b1, [128:256) b2

    int tid = threadIdx.x, warp = tid >> 5, lane = tid & 31;
    int bid = blockIdx.x;

    // ---- stage all weights + biases once ----
    {
        const size_t istr = (size_t)HID * SA;
        const size_t lstr = (size_t)2 * LAYERS * HID * SA;
        const float4* srcs[4] = {
            (const float4*)(g_wt + (size_t)l * istr),
            (const float4*)(g_wt + lstr + (size_t)l * istr),
            (const float4*)(g_wt + (size_t)(LAYERS + l) * istr),
            (const float4*)(g_wt + lstr + (size_t)(LAYERS + l) * istr) };
#pragma unroll
        for (int q = 0; q < 4; q++) {
            float4* d = (float4*)(S + q * WTILE_B);
            for (int i = tid; i < WTILE_B / 16; i += 256) d[i] = srcs[q][i];
        }
        if (tid < 128) sbias[tid] = __ldg(b1 + tid);
        else sbias[tid] = __ldg(b2 + tid - 128);
    }

    int m0 = warp * 16;
    int g = lane >> 3;
    int arow_off = (lane & 7) + ((g & 1) << 3);
    int akoff    = (g >> 1) << 3;
    int brow_off = (lane & 7) + ((g >> 1) << 3);
    int bkoff    = (g & 1) << 3;
    int cb = (lane & 3) * 2;      // col pair offset within an 8-col n-tile
    int rA = m0 + (lane >> 2), rB = rA + 8;

    // first tile prefetch (warp-private)
    prefetch_rows(aA, m0, bid * NODES_PT + m0, lane);
    CP_COMMIT();
    __syncthreads();              // weights + biases visible to all

    for (int t = bid; t < NT; t += NBLK) {
        int node0 = t * NODES_PT;
        CP_WAIT(0);               // this warp's A slice resident
        __syncwarp();

        // ================= GEMM 1: acc[16 ntiles][4] =================
        float acc[16][4];
#pragma unroll
        for (int n = 0; n < 16; n++)
#pragma unroll
            for (int c = 0; c < 4; c++) acc[n][c] = 0.f;

#pragma unroll
        for (int kb = 0; kb < 8; kb++) {
            uint32_t ah[4], al[4];
            uint32_t aro = (uint32_t)((m0 + arow_off) * SA + kb * 16 + akoff) * 2;
            ldm_x4(ah, aA + aro);
            ldm_x4(al, aA + AHALF_B + aro);
#pragma unroll
            for (int nb = 0; nb < 8; nb++) {
                uint32_t bh[4], bl[4];
                uint32_t ro = (uint32_t)((nb * 16 + brow_off) * SA + kb * 16 + bkoff) * 2;
                ldm_x4(bh, aW1h + ro);
                ldm_x4(bl, aW1l + ro);
                mma16816(acc[2 * nb],     ah, bh[0], bh[1]);
                mma16816(acc[2 * nb],     ah, bl[0], bl[1]);
                mma16816(acc[2 * nb],     al, bh[0], bh[1]);
                mma16816(acc[2 * nb + 1], ah, bh[2], bh[3]);
                mma16816(acc[2 * nb + 1], ah, bl[2], bl[3]);
                mma16816(acc[2 * nb + 1], al, bh[2], bh[3]);
            }
        }
        __syncwarp();
        // A slice consumed (warp-private) -> prefetch next tile now; the load
        // overlaps convert + GEMM2 + epilogue below.
        {
            int tn = t + NBLK;
            if (tn < NT) {
                prefetch_rows(aA, m0, tn * NODES_PT + m0, lane);
                CP_COMMIT();
            }
        }

        // ===== convert: H = relu(acc + b1) -> GEMM2 A fragments (regs) =====
        // k-block j uses ntiles 2j (k 0-7) and 2j+1 (k 8-15):
        //   a0=pk(c0,c1 of 2j) a1=pk(c2,c3 of 2j) a2=pk(c0,c1 of 2j+1) a3=...
        uint32_t ahi[8][4], alo[8][4];
#pragma unroll
        for (int j = 0; j < 8; j++) {
#pragma unroll
            for (int p = 0; p < 2; p++) {
                int nt = 2 * j + p;
                float bb0 = sbias[8 * nt + cb], bb1 = sbias[8 * nt + cb + 1];
                float v0 = fmaxf(acc[nt][0] + bb0, 0.f);
                float v1 = fmaxf(acc[nt][1] + bb1, 0.f);
                float v2 = fmaxf(acc[nt][2] + bb0, 0.f);
                float v3 = fmaxf(acc[nt][3] + bb1, 0.f);
                __nv_bfloat16 h0 = __float2bfloat16(v0), h1 = __float2bfloat16(v1);
                __nv_bfloat16 h2 = __float2bfloat16(v2), h3 = __float2bfloat16(v3);
                __nv_bfloat16 q0 = __float2bfloat16(v0 - __bfloat162float(h0));
                __nv_bfloat16 q1 = __float2bfloat16(v1 - __bfloat162float(h1));
                __nv_bfloat16 q2 = __float2bfloat16(v2 - __bfloat162float(h2));
                __nv_bfloat16 q3 = __float2bfloat16(v3 - __bfloat162float(h3));
                ahi[j][2 * p]     = pk(h0, h1);
                ahi[j][2 * p + 1] = pk(h2, h3);
                alo[j][2 * p]     = pk(q0, q1);
                alo[j][2 * p + 1] = pk(q2, q3);
            }
        }

        // ================= GEMM 2 (A from registers) =================
        float acc2[16][4];
#pragma unroll
        for (int n = 0; n < 16; n++)
#pragma unroll
            for (int c = 0; c < 4; c++) acc2[n][c] = 0.f;

#pragma unroll
        for (int kb = 0; kb < 8; kb++) {
#pragma unroll
            for (int nb = 0; nb < 8; nb++) {
                uint32_t bh[4], bl[4];
                uint32_t ro = (uint32_t)((nb * 16 + brow_off) * SA + kb * 16 + bkoff) * 2;
                ldm_x4(bh, aW2h + ro);
                ldm_x4(bl, aW2l + ro);
                mma16816(acc2[2 * nb],     ahi[kb], bh[0], bh[1]);
                mma16816(acc2[2 * nb],     ahi[kb], bl[0], bl[1]);
                mma16816(acc2[2 * nb],     alo[kb], bh[0], bh[1]);
                mma16816(acc2[2 * nb + 1], ahi[kb], bh[2], bh[3]);
                mma16816(acc2[2 * nb + 1], ahi[kb], bl[2], bl[3]);
                mma16816(acc2[2 * nb + 1], alo[kb], bh[2], bh[3]);
            }
        }

        // ============ epilogue: x = relu(acc2 + b2) -> g_x ============
        {
            int gA = node0 + rA, gB = node0 + rB;
#pragma unroll
            for (int nt = 0; nt < 16; nt++) {
                int col = 8 * nt + cb;
                float bb0 = sbias[128 + col], bb1 = sbias[128 + col + 1];
                if (gA < N_NODES) {
                    float2 v = make_float2(fmaxf(acc2[nt][0] + bb0, 0.f),
                                           fmaxf(acc2[nt][1] + bb1, 0.f));
                    *(float2*)(g_x + (size_t)gA * HID + col) = v;
                }
                if (gB < N_NODES) {
                    float2 v = make_float2(fmaxf(acc2[nt][2] + bb0, 0.f),
                                           fmaxf(acc2[nt][3] + bb1, 0.f));
                    *(float2*)(g_x + (size_t)gB * HID + col) = v;
                }
            }
        }
        // no block barrier: A buffer region, H, and output rows are all
        // warp-private; next iteration's CP_WAIT orders the prefetch.
    }
}

// ---------------------------------------------------------------------------
// Global mean pool
// ---------------------------------------------------------------------------
__global__ void pool_kernel(const int* __restrict__ batch,
                            float* __restrict__ out) {
    int g = blockIdx.x;
    __shared__ int s_range[2];
    if (threadIdx.x == 0) {
        int lo = 0, hi = N_NODES;
        while (lo < hi) { int m = (lo + hi) >> 1; if (batch[m] < g) lo = m + 1; else hi = m; }
        s_range[0] = lo;
        lo = 0; hi = N_NODES;
        while (lo < hi) { int m = (lo + hi) >> 1; if (batch[m] < g + 1) lo = m + 1; else hi = m; }
        s_range[1] = lo;
    }
    __syncthreads();
    int start = s_range[0], end = s_range[1];
    float sum = 0.f;
    for (int n = start; n < end; n++)
        sum += g_x[(size_t)n * HID + threadIdx.x];
    float cnt = (float)(end - start);
    out[g * HID + threadIdx.x] = sum / fmaxf(cnt, 1.0f);
}

// ---------------------------------------------------------------------------
// Inputs: x_tokens, edge_index, batch, emb, W1, b1, W2, b2
// ---------------------------------------------------------------------------
extern "C" void kernel_launch(void* const* d_in, const int* in_sizes, int n_in,
                              void* d_out, int out_size) {
    const int*   tok   = (const int*)  d_in[0];
    const int*   ei    = (const int*)  d_in[1];
    const int*   batch = (const int*)  d_in[2];
    const float* emb   = (const float*)d_in[3];
    const float* W1    = (const float*)d_in[4];
    const float* b1    = (const float*)d_in[5];
    const float* W2    = (const float*)d_in[6];
    const float* b2    = (const float*)d_in[7];
    float* out = (float*)d_out;

    cudaFuncSetAttribute(mlp_mma, cudaFuncAttributeMaxDynamicSharedMemorySize,
                         SMEM_BYTES);

    prep_w<<<(2 * LAYERS * HID * HID + 255) / 256, 256>>>(W1, W2);
    embed_kernel<<<(N_NODES * 32 + 255) / 256, 256>>>(tok, emb);

    k_hist <<<(N_EDGES + 255) / 256, 256>>>(ei);
    k_scan1<<<SCAN_NB, SCAN_B>>>();
    k_scan2<<<1, 32>>>();
    k_scan3<<<(N_NODES + 255) / 256, 256>>>();
    k_fill <<<(N_EDGES + 255) / 256, 256>>>(ei);

    for (int l = 0; l < LAYERS; l++) {
        gather_kernel<<<(N_NODES * 32 + 255) / 256, 256>>>();
        mlp_mma<<<NBLK, 256, SMEM_BYTES>>>(
            b1 + (size_t)l * HID, b2 + (size_t)l * HID, l);
    }

    pool_kernel<<<N_GRAPHS, HID>>>(batch, out);
}